// round 2
// baseline (speedup 1.0000x reference)
#include <cuda_runtime.h>

// Fused 2-layer LSTM (B=4096,S=512,F=1,H=64) + dense 64->32->24 head.
// 128 blocks x 128 threads; block owns 32 batches for the whole sequence.
// Weights k-major in smem; batch-paired f32x2 FMA inner loops.

#define NT   128
#define TB   32
#define NBLK 128
#define SEQ  512

typedef unsigned long long u64;

// shared-memory float offsets
#define WT1_O 0                      // [64 k][256 rows]
#define WT2_O (WT1_O + 64 * 256)     // [128 k][256 rows]
#define HA_O  (WT2_O + 128 * 256)    // [128 rows][32 batch] (pair-swizzled)
#define XT_O  (HA_O + 128 * 32)      // [32 batch][68 pitch] x tile (64 steps)
#define B1_O  (XT_O + 32 * 68)       // 256: b_ih1+b_hh1
#define B2_O  (B1_O + 256)           // 256: b_ih2+b_hh2
#define WI1_O (B2_O + 256)           // 256: W_ih1[:,0]
#define SM_FLOATS (WI1_O + 256)
#define SM_BYTES  (SM_FLOATS * 4)    // 224768 bytes

__device__ __forceinline__ u64 splat2(float v) {
    u64 r; unsigned u = __float_as_uint(v);
    asm("mov.b64 %0, {%1, %1};" : "=l"(r) : "r"(u));
    return r;
}
__device__ __forceinline__ u64 pack2(float a, float b) {
    u64 r; unsigned ua = __float_as_uint(a), ub = __float_as_uint(b);
    asm("mov.b64 %0, {%1, %2};" : "=l"(r) : "r"(ua), "r"(ub));
    return r;
}
__device__ __forceinline__ void fma2(u64& d, u64 a, u64 b) {
    asm("fma.rn.f32x2 %0, %1, %2, %0;" : "+l"(d) : "l"(a), "l"(b));
}
__device__ __forceinline__ float lo32(u64 v) { return __uint_as_float((unsigned)v); }
__device__ __forceinline__ float hi32(u64 v) { return __uint_as_float((unsigned)(v >> 32)); }

__device__ __forceinline__ float sigf(float x) {
    return __fdividef(1.f, 1.f + __expf(-x));
}
__device__ __forceinline__ float tanhf_(float x) {
    float xx = fmaxf(x, -30.f);
    float e  = __expf(-2.f * xx);
    return __fdividef(1.f - e, 1.f + e);
}

// swizzled h-buffer index for (row 0..127, local batch 0..31)
__device__ __forceinline__ int ha_idx(int row, int b) {
    int pb = b >> 1;
    int ps = pb ^ ((row >> 1) & 15);
    return row * 32 + (ps << 1) + (b & 1);
}

extern __shared__ float sm[];

__global__ void __launch_bounds__(NT, 1)
lstm_fused_kernel(const float* __restrict__ x,
                  const float* __restrict__ W_ih1, const float* __restrict__ W_hh1,
                  const float* __restrict__ b_ih1, const float* __restrict__ b_hh1,
                  const float* __restrict__ W_ih2, const float* __restrict__ W_hh2,
                  const float* __restrict__ b_ih2, const float* __restrict__ b_hh2,
                  const float* __restrict__ W_d1, const float* __restrict__ b_d1,
                  const float* __restrict__ W_d2, const float* __restrict__ b_d2,
                  float* __restrict__ out)
{
    const int tid = threadIdx.x;
    const int hg  = tid & 31;   // hidden-pair group (lane)
    const int bg  = tid >> 5;   // batch group (warp)
    const int b0  = blockIdx.x * TB;

    // ---- stage weights into smem (k-major transpose) ----
    for (int i = tid; i < 256 * 64; i += NT) {
        int r = i >> 6, k = i & 63;
        sm[WT1_O + k * 256 + r] = W_hh1[i];
    }
    for (int i = tid; i < 256 * 64; i += NT) {
        int r = i >> 6, k = i & 63;
        sm[WT2_O + k * 256 + r] = W_ih2[i];
    }
    for (int i = tid; i < 256 * 64; i += NT) {
        int r = i >> 6, k = i & 63;
        sm[WT2_O + (64 + k) * 256 + r] = W_hh2[i];
    }
    for (int i = tid; i < 256; i += NT) {
        sm[B1_O + i]  = b_ih1[i] + b_hh1[i];
        sm[B2_O + i]  = b_ih2[i] + b_hh2[i];
        sm[WI1_O + i] = W_ih1[i];
    }
    for (int i = tid; i < 128 * 32; i += NT) sm[HA_O + i] = 0.f;
    __syncthreads();

    u64   acc[4][2][4];          // [gate][unit][batch-pair]
    float c1[2][8], c2[2][8];
    #pragma unroll
    for (int u = 0; u < 2; ++u)
        #pragma unroll
        for (int j = 0; j < 8; ++j) { c1[u][j] = 0.f; c2[u][j] = 0.f; }

    for (int t = 0; t < SEQ; ++t) {
        // ---- refill x tile every 64 steps ----
        if ((t & 63) == 0) {
            for (int i = tid; i < 32 * 16; i += NT) {
                int row = i >> 4, q = i & 15;
                float4 v = *(const float4*)(x + (size_t)(b0 + row) * SEQ + t + q * 4);
                *(float4*)&sm[XT_O + row * 68 + q * 4] = v;
            }
            __syncthreads();
        }
        const int tt = t & 63;

        // ================= layer 1: z = x*W_ih1 + bias + h1 @ W_hh1^T =====
        {
            float xv[8];
            #pragma unroll
            for (int j = 0; j < 8; ++j) xv[j] = sm[XT_O + (bg * 8 + j) * 68 + tt];
            #pragma unroll
            for (int g = 0; g < 4; ++g)
                #pragma unroll
                for (int u = 0; u < 2; ++u) {
                    int r = g * 64 + 2 * hg + u;
                    float w = sm[WI1_O + r], bb = sm[B1_O + r];
                    #pragma unroll
                    for (int p = 0; p < 4; ++p)
                        acc[g][u][p] = pack2(fmaf(xv[2 * p], w, bb),
                                             fmaf(xv[2 * p + 1], w, bb));
                }
        }
        #pragma unroll 2
        for (int k = 0; k < 64; ++k) {
            int sw = (k >> 1) & 15;
            u64 hp[4];
            #pragma unroll
            for (int p = 0; p < 4; ++p) {
                int pb = bg * 4 + p;
                hp[p] = *(const u64*)&sm[HA_O + k * 32 + ((pb ^ sw) << 1)];
            }
            #pragma unroll
            for (int g = 0; g < 4; ++g) {
                u64 wv = *(const u64*)&sm[WT1_O + k * 256 + g * 64 + 2 * hg];
                u64 w0 = splat2(lo32(wv)), w1 = splat2(hi32(wv));
                #pragma unroll
                for (int p = 0; p < 4; ++p) {
                    fma2(acc[g][0][p], w0, hp[p]);
                    fma2(acc[g][1][p], w1, hp[p]);
                }
            }
        }
        __syncthreads();

        // ---- pointwise layer 1 -> h1 into HA rows [0,64) ----
        #pragma unroll
        for (int u = 0; u < 2; ++u) {
            int row = 2 * hg + u;
            #pragma unroll
            for (int p = 0; p < 4; ++p) {
                int pb = bg * 4 + p;
                int base = HA_O + row * 32 + ((pb ^ (hg & 15)) << 1);
                #pragma unroll
                for (int jj = 0; jj < 2; ++jj) {
                    int j = 2 * p + jj;
                    float zi = jj ? hi32(acc[0][u][p]) : lo32(acc[0][u][p]);
                    float zf = jj ? hi32(acc[1][u][p]) : lo32(acc[1][u][p]);
                    float zg = jj ? hi32(acc[2][u][p]) : lo32(acc[2][u][p]);
                    float zo = jj ? hi32(acc[3][u][p]) : lo32(acc[3][u][p]);
                    float c = sigf(zf) * c1[u][j] + sigf(zi) * tanhf_(zg);
                    c1[u][j] = c;
                    sm[base + jj] = sigf(zo) * tanhf_(c);
                }
            }
        }
        __syncthreads();

        // ================= layer 2: K=128 against [h1_t | h2_{t-1}] =======
        #pragma unroll
        for (int g = 0; g < 4; ++g)
            #pragma unroll
            for (int u = 0; u < 2; ++u) {
                u64 bb = splat2(sm[B2_O + g * 64 + 2 * hg + u]);
                #pragma unroll
                for (int p = 0; p < 4; ++p) acc[g][u][p] = bb;
            }
        #pragma unroll 2
        for (int k = 0; k < 128; ++k) {
            int sw = (k >> 1) & 15;
            u64 hp[4];
            #pragma unroll
            for (int p = 0; p < 4; ++p) {
                int pb = bg * 4 + p;
                hp[p] = *(const u64*)&sm[HA_O + k * 32 + ((pb ^ sw) << 1)];
            }
            #pragma unroll
            for (int g = 0; g < 4; ++g) {
                u64 wv = *(const u64*)&sm[WT2_O + k * 256 + g * 64 + 2 * hg];
                u64 w0 = splat2(lo32(wv)), w1 = splat2(hi32(wv));
                #pragma unroll
                for (int p = 0; p < 4; ++p) {
                    fma2(acc[g][0][p], w0, hp[p]);
                    fma2(acc[g][1][p], w1, hp[p]);
                }
            }
        }
        __syncthreads();

        // ---- pointwise layer 2 -> h2 into HA rows [64,128) ----
        #pragma unroll
        for (int u = 0; u < 2; ++u) {
            int row = 64 + 2 * hg + u;
            #pragma unroll
            for (int p = 0; p < 4; ++p) {
                int pb = bg * 4 + p;
                int base = HA_O + row * 32 + ((pb ^ (hg & 15)) << 1);
                #pragma unroll
                for (int jj = 0; jj < 2; ++jj) {
                    int j = 2 * p + jj;
                    float zi = jj ? hi32(acc[0][u][p]) : lo32(acc[0][u][p]);
                    float zf = jj ? hi32(acc[1][u][p]) : lo32(acc[1][u][p]);
                    float zg = jj ? hi32(acc[2][u][p]) : lo32(acc[2][u][p]);
                    float zo = jj ? hi32(acc[3][u][p]) : lo32(acc[3][u][p]);
                    float c = sigf(zf) * c2[u][j] + sigf(zi) * tanhf_(zg);
                    c2[u][j] = c;
                    sm[base + jj] = sigf(zo) * tanhf_(c);
                }
            }
        }
        __syncthreads();
    }

    // ================= dense head on h2_last (HA rows 64..127) =============
    for (int i = tid; i < 32 * 64; i += NT) sm[XT_O + i] = W_d1[i];     // XT reused
    for (int i = tid; i < 24 * 32; i += NT) sm[WT1_O + i] = W_d2[i];    // WT1 reused
    if (tid < 32) sm[WT1_O + 768 + tid] = b_d1[tid];
    if (tid < 24) sm[WT1_O + 800 + tid] = b_d2[tid];
    __syncthreads();

    for (int idx = tid; idx < 32 * 32; idx += NT) {       // relu(h2 @ W_d1^T + b)
        int b = idx >> 5, jj = idx & 31;
        float a = sm[WT1_O + 768 + jj];
        #pragma unroll 8
        for (int k = 0; k < 64; ++k)
            a += sm[HA_O + ha_idx(64 + k, b)] * sm[XT_O + jj * 64 + k];
        sm[HA_O + b * 32 + jj] = fmaxf(a, 0.f);           // y1 into HA rows 0..31
    }
    __syncthreads();
    for (int idx = tid; idx < 32 * 24; idx += NT) {       // y1 @ W_d2^T + b
        int b = idx / 24, o = idx - b * 24;
        float a = sm[WT1_O + 800 + o];
        #pragma unroll 8
        for (int j = 0; j < 32; ++j)
            a += sm[HA_O + b * 32 + j] * sm[WT1_O + o * 32 + j];
        out[(size_t)(b0 + b) * 24 + o] = a;
    }
}

extern "C" void kernel_launch(void* const* d_in, const int* in_sizes, int n_in,
                              void* d_out, int out_size)
{
    const float* x     = (const float*)d_in[0];
    const float* W_ih1 = (const float*)d_in[1];
    const float* W_hh1 = (const float*)d_in[2];
    const float* b_ih1 = (const float*)d_in[3];
    const float* b_hh1 = (const float*)d_in[4];
    const float* W_ih2 = (const float*)d_in[5];
    const float* W_hh2 = (const float*)d_in[6];
    const float* b_ih2 = (const float*)d_in[7];
    const float* b_hh2 = (const float*)d_in[8];
    const float* W_d1  = (const float*)d_in[9];
    const float* b_d1  = (const float*)d_in[10];
    const float* W_d2  = (const float*)d_in[11];
    const float* b_d2  = (const float*)d_in[12];
    float* out = (float*)d_out;

    cudaFuncSetAttribute(lstm_fused_kernel,
                         cudaFuncAttributeMaxDynamicSharedMemorySize, SM_BYTES);
    lstm_fused_kernel<<<NBLK, NT, SM_BYTES>>>(
        x, W_ih1, W_hh1, b_ih1, b_hh1, W_ih2, W_hh2, b_ih2, b_hh2,
        W_d1, b_d1, W_d2, b_d2, out);
}

// round 3
// speedup vs baseline: 1.2230x; 1.2230x over previous
#include <cuda_runtime.h>

// Fused 2-layer LSTM (B=4096,S=512,F=1,H=64) + dense 64->32->24 head.
// 128 blocks x 256 threads. Block owns 32 batches for the whole sequence.
// Merged phase: GEMM2(t) + GEMM1(t+1) share one k-loop -> 2 barriers/step.
// Batch-paired fp32x2 FMA; weights k-major in smem; h buffer octet-rotated.

#define NT   256
#define TB   32
#define NBLK 128
#define SEQ  512

typedef unsigned long long u64;

// shared memory float offsets
#define WT1_O 0                       // [64 k][256 rows]
#define WT2_O (WT1_O + 64 * 256)      // [128 k][256 rows]
#define HA_O  (WT2_O + 128 * 256)     // [128 rows][32] octet-rotated
#define XT_O  (HA_O + 128 * 32)       // [64 steps][34 pitch] x tile
#define B1_O  (XT_O + 64 * 34)        // 256
#define B2_O  (B1_O + 256)            // 256
#define WI1_O (B2_O + 256)            // 256
#define HW_O  (WI1_O + 256)           // head: W_d2(768) + b_d1(32) + b_d2(24)
#define SM_FLOATS (HW_O + 832)
#define SM_BYTES  (SM_FLOATS * 4)     // 228096 bytes

__device__ __forceinline__ u64 splat2(float v) {
    u64 r; unsigned u = __float_as_uint(v);
    asm("mov.b64 %0, {%1, %1};" : "=l"(r) : "r"(u));
    return r;
}
__device__ __forceinline__ void fma2(u64& d, u64 a, u64 b) {
    asm("fma.rn.f32x2 %0, %1, %2, %0;" : "+l"(d) : "l"(a), "l"(b));
}
__device__ __forceinline__ float lo32(u64 v) { return __uint_as_float((unsigned)v); }
__device__ __forceinline__ float hi32(u64 v) { return __uint_as_float((unsigned)(v >> 32)); }

__device__ __forceinline__ float sigf(float x) {
    return __fdividef(1.f, 1.f + __expf(-x));
}
__device__ __forceinline__ float tanhf_(float x) {
    float xx = fmaxf(x, -30.f);
    float e  = __expf(-2.f * xx);
    return __fdividef(1.f - e, 1.f + e);
}

extern __shared__ float sm[];

// pointwise LSTM cell update for 8 batches; writes h (8 floats) to hdst
__device__ __forceinline__ void pointwise(const u64 acc[4][4], float c[8], float* hdst) {
    float hv[8];
    #pragma unroll
    for (int p = 0; p < 4; ++p) {
        #pragma unroll
        for (int q = 0; q < 2; ++q) {
            int j = 2 * p + q;
            float zi = q ? hi32(acc[0][p]) : lo32(acc[0][p]);
            float zf = q ? hi32(acc[1][p]) : lo32(acc[1][p]);
            float zg = q ? hi32(acc[2][p]) : lo32(acc[2][p]);
            float zo = q ? hi32(acc[3][p]) : lo32(acc[3][p]);
            float cc = sigf(zf) * c[j] + sigf(zi) * tanhf_(zg);
            c[j] = cc;
            hv[j] = sigf(zo) * tanhf_(cc);
        }
    }
    *(float4*)&hdst[0] = make_float4(hv[0], hv[1], hv[2], hv[3]);
    *(float4*)&hdst[4] = make_float4(hv[4], hv[5], hv[6], hv[7]);
}

__device__ __forceinline__ void load_xtile(const float* __restrict__ x,
                                           int b0, int base, int tid) {
    #pragma unroll
    for (int it = 0; it < 2; ++it) {
        int i = tid + it * NT;
        int row = i >> 4, q = (i & 15) << 2;
        float4 v = *(const float4*)(x + (size_t)(b0 + row) * SEQ + base + q);
        sm[XT_O + (q + 0) * 34 + row] = v.x;
        sm[XT_O + (q + 1) * 34 + row] = v.y;
        sm[XT_O + (q + 2) * 34 + row] = v.z;
        sm[XT_O + (q + 3) * 34 + row] = v.w;
    }
}

__global__ void __launch_bounds__(NT, 1)
lstm_fused_kernel(const float* __restrict__ x,
                  const float* __restrict__ W_ih1, const float* __restrict__ W_hh1,
                  const float* __restrict__ b_ih1, const float* __restrict__ b_hh1,
                  const float* __restrict__ W_ih2, const float* __restrict__ W_hh2,
                  const float* __restrict__ b_ih2, const float* __restrict__ b_hh2,
                  const float* __restrict__ W_d1, const float* __restrict__ b_d1,
                  const float* __restrict__ W_d2, const float* __restrict__ b_d2,
                  float* __restrict__ out)
{
    const int tid  = threadIdx.x;
    const int lane = tid & 31;
    const int wrp  = tid >> 5;
    const int hid  = ((wrp & 1) << 5) | lane;   // 0..63: hidden unit
    const int bg   = wrp >> 1;                  // 0..3 : batch octet
    const int b0   = blockIdx.x * TB;
    const int octh = ((bg + hid) & 3) << 3;     // rotation for h writes

    // ---- stage weights (k-major) ----
    for (int i = tid; i < 256 * 64; i += NT) {
        int r = i >> 6, k = i & 63;
        sm[WT1_O + k * 256 + r] = W_hh1[i];
    }
    for (int i = tid; i < 256 * 64; i += NT) {
        int r = i >> 6, k = i & 63;
        sm[WT2_O + k * 256 + r] = W_ih2[i];
    }
    for (int i = tid; i < 256 * 64; i += NT) {
        int r = i >> 6, k = i & 63;
        sm[WT2_O + (64 + k) * 256 + r] = W_hh2[i];
    }
    for (int i = tid; i < 256; i += NT) {
        sm[B1_O + i]  = b_ih1[i] + b_hh1[i];
        sm[B2_O + i]  = b_ih2[i] + b_hh2[i];
        sm[WI1_O + i] = W_ih1[i];
    }
    for (int i = tid; i < 128 * 32; i += NT) sm[HA_O + i] = 0.f;
    load_xtile(x, b0, 0, tid);
    __syncthreads();

    u64   acc1[4][4], acc2[4][4];
    float c1[8], c2[8];
    #pragma unroll
    for (int j = 0; j < 8; ++j) { c1[j] = 0.f; c2[j] = 0.f; }

    float* h1dst = &sm[HA_O + hid * 32 + octh];
    float* h2dst = &sm[HA_O + (64 + hid) * 32 + octh];
    const float* w1base = sm + WT1_O + hid;
    const float* w2base = sm + WT2_O + hid;

    // ---- prologue: GEMM1(0) is bias + x0*w (h1 = 0), then PW1(0) ----
    {
        u64 xp[4];
        #pragma unroll
        for (int p = 0; p < 4; ++p)
            xp[p] = *(const u64*)&sm[XT_O + 0 * 34 + bg * 8 + 2 * p];
        #pragma unroll
        for (int g = 0; g < 4; ++g) {
            u64 sb = splat2(sm[B1_O + g * 64 + hid]);
            u64 sw = splat2(sm[WI1_O + g * 64 + hid]);
            #pragma unroll
            for (int p = 0; p < 4; ++p) { acc1[g][p] = sb; fma2(acc1[g][p], sw, xp[p]); }
        }
        pointwise(acc1, c1, h1dst);
    }
    __syncthreads();

    // ---- main loop: phase A = GEMM2(t) + GEMM1(t+1); phase B = PW2(t) + PW1(t+1)
    for (int t = 0; t < SEQ; ++t) {
        if (((t + 1) & 63) == 0 && (t + 1) < SEQ) {
            load_xtile(x, b0, t + 1, tid);
            __syncthreads();
        }
        const int tt = ((t + 1) < SEQ ? (t + 1) : t) & 63;

        // init acc2 = bias2 ; acc1 = bias1 + x(t+1)*w_ih1
        #pragma unroll
        for (int g = 0; g < 4; ++g) {
            u64 s = splat2(sm[B2_O + g * 64 + hid]);
            #pragma unroll
            for (int p = 0; p < 4; ++p) acc2[g][p] = s;
        }
        {
            u64 xp[4];
            #pragma unroll
            for (int p = 0; p < 4; ++p)
                xp[p] = *(const u64*)&sm[XT_O + tt * 34 + bg * 8 + 2 * p];
            #pragma unroll
            for (int g = 0; g < 4; ++g) {
                u64 sb = splat2(sm[B1_O + g * 64 + hid]);
                u64 sw = splat2(sm[WI1_O + g * 64 + hid]);
                #pragma unroll
                for (int p = 0; p < 4; ++p) { acc1[g][p] = sb; fma2(acc1[g][p], sw, xp[p]); }
            }
        }

        #pragma unroll 2
        for (int k = 0; k < 64; ++k) {
            int ha = HA_O + (k << 5) + (((bg + k) & 3) << 3);
            ulonglong2 q0 = *(const ulonglong2*)&sm[ha];
            ulonglong2 q1 = *(const ulonglong2*)&sm[ha + 4];
            ulonglong2 q2 = *(const ulonglong2*)&sm[ha + 2048];
            ulonglong2 q3 = *(const ulonglong2*)&sm[ha + 2048 + 4];
            u64 hp1[4] = { q0.x, q0.y, q1.x, q1.y };
            u64 hp2[4] = { q2.x, q2.y, q3.x, q3.y };
            #pragma unroll
            for (int g = 0; g < 4; ++g) {
                u64 s1 = splat2(w1base[k * 256 + g * 64]);
                #pragma unroll
                for (int p = 0; p < 4; ++p) fma2(acc1[g][p], s1, hp1[p]);
                u64 s2 = splat2(w2base[k * 256 + g * 64]);
                #pragma unroll
                for (int p = 0; p < 4; ++p) fma2(acc2[g][p], s2, hp1[p]);
                u64 s3 = splat2(w2base[(64 + k) * 256 + g * 64]);
                #pragma unroll
                for (int p = 0; p < 4; ++p) fma2(acc2[g][p], s3, hp2[p]);
            }
        }
        __syncthreads();

        pointwise(acc2, c2, h2dst);                    // h2[t]
        if (t + 1 < SEQ) pointwise(acc1, c1, h1dst);   // h1[t+1]
        __syncthreads();
    }

    // ---- dense head on h2[511] (HA rows 64..127) ----
    for (int i = tid; i < 32 * 64; i += NT) sm[XT_O + i] = W_d1[i];
    for (int i = tid; i < 24 * 32; i += NT) sm[HW_O + i] = W_d2[i];
    if (tid < 32) sm[HW_O + 768 + tid] = b_d1[tid];
    if (tid < 24) sm[HW_O + 800 + tid] = b_d2[tid];
    __syncthreads();

    for (int idx = tid; idx < 32 * 32; idx += NT) {     // relu(h2 @ W_d1^T + b)
        int b = idx >> 5, j = idx & 31;
        int ob = b >> 3, bl = b & 7;
        float a = sm[HW_O + 768 + j];
        #pragma unroll 8
        for (int k = 0; k < 64; ++k) {
            float hv = sm[HA_O + (64 + k) * 32 + (((ob + k) & 3) << 3) + bl];
            a += hv * sm[XT_O + j * 64 + k];
        }
        sm[HA_O + b * 32 + j] = fmaxf(a, 0.f);          // y1 -> HA rows 0..31
    }
    __syncthreads();
    for (int idx = tid; idx < 32 * 24; idx += NT) {     // y1 @ W_d2^T + b
        int b = idx / 24, o = idx - b * 24;
        float a = sm[HW_O + 800 + o];
        #pragma unroll 8
        for (int j = 0; j < 32; ++j)
            a += sm[HA_O + b * 32 + j] * sm[HW_O + o * 32 + j];
        out[(size_t)(b0 + b) * 24 + o] = a;
    }
}

extern "C" void kernel_launch(void* const* d_in, const int* in_sizes, int n_in,
                              void* d_out, int out_size)
{
    const float* x     = (const float*)d_in[0];
    const float* W_ih1 = (const float*)d_in[1];
    const float* W_hh1 = (const float*)d_in[2];
    const float* b_ih1 = (const float*)d_in[3];
    const float* b_hh1 = (const float*)d_in[4];
    const float* W_ih2 = (const float*)d_in[5];
    const float* W_hh2 = (const float*)d_in[6];
    const float* b_ih2 = (const float*)d_in[7];
    const float* b_hh2 = (const float*)d_in[8];
    const float* W_d1  = (const float*)d_in[9];
    const float* b_d1  = (const float*)d_in[10];
    const float* W_d2  = (const float*)d_in[11];
    const float* b_d2  = (const float*)d_in[12];
    float* out = (float*)d_out;

    cudaFuncSetAttribute(lstm_fused_kernel,
                         cudaFuncAttributeMaxDynamicSharedMemorySize, SM_BYTES);
    lstm_fused_kernel<<<NBLK, NT, SM_BYTES>>>(
        x, W_ih1, W_hh1, b_ih1, b_hh1, W_ih2, W_hh2, b_ih2, b_hh2,
        W_d1, b_d1, W_d2, b_d2, out);
}

// round 4
// speedup vs baseline: 1.3094x; 1.0707x over previous
#include <cuda_runtime.h>

// Fused 2-layer LSTM (B=4096,S=512,F=1,H=64) + dense 64->32->24 head.
// 128 blocks x 256 threads; block owns 32 batches for the whole sequence.
// Merged GEMM2(t)+GEMM1(t+1) k-loop, gate-packed LDS.128 weights,
// register double-buffered pipeline, batch-paired fp32x2 FMA.

#define NT   256
#define TB   32
#define NBLK 128
#define SEQ  512

typedef unsigned long long u64;

// shared memory float offsets
#define WT1_O 0                       // [64 k][hid*4+gate] (256/row)
#define WT2_O (WT1_O + 64 * 256)      // [128 k][hid*4+gate]
#define HA_O  (WT2_O + 128 * 256)     // [128 rows][32] octet-rotated
#define XT_O  (HA_O + 128 * 32)       // [64 steps][34 pitch] x tile
#define B1_O  (XT_O + 64 * 34)        // 256
#define B2_O  (B1_O + 256)            // 256
#define WI1_O (B2_O + 256)            // 256
#define HW_O  (WI1_O + 256)           // head: W_d2(768) + b_d1(32) + b_d2(24)
#define SM_FLOATS (HW_O + 832)
#define SM_BYTES  (SM_FLOATS * 4)     // 228096 bytes

__device__ __forceinline__ u64 splat2(float v) {
    u64 r; unsigned u = __float_as_uint(v);
    asm("mov.b64 %0, {%1, %1};" : "=l"(r) : "r"(u));
    return r;
}
__device__ __forceinline__ void fma2(u64& d, u64 a, u64 b) {
    asm("fma.rn.f32x2 %0, %1, %2, %0;" : "+l"(d) : "l"(a), "l"(b));
}
__device__ __forceinline__ float lo32(u64 v) { return __uint_as_float((unsigned)v); }
__device__ __forceinline__ float hi32(u64 v) { return __uint_as_float((unsigned)(v >> 32)); }

__device__ __forceinline__ float sigf(float x) {
    return __fdividef(1.f, 1.f + __expf(-x));
}
__device__ __forceinline__ float tanhf_(float x) {
    float xx = fmaxf(x, -30.f);
    float e  = __expf(-2.f * xx);
    return __fdividef(1.f - e, 1.f + e);
}

extern __shared__ float sm[];

__device__ __forceinline__ void pointwise(const u64 acc[4][4], float c[8], float* hdst) {
    float hv[8];
    #pragma unroll
    for (int p = 0; p < 4; ++p) {
        #pragma unroll
        for (int q = 0; q < 2; ++q) {
            int j = 2 * p + q;
            float zi = q ? hi32(acc[0][p]) : lo32(acc[0][p]);
            float zf = q ? hi32(acc[1][p]) : lo32(acc[1][p]);
            float zg = q ? hi32(acc[2][p]) : lo32(acc[2][p]);
            float zo = q ? hi32(acc[3][p]) : lo32(acc[3][p]);
            float cc = sigf(zf) * c[j] + sigf(zi) * tanhf_(zg);
            c[j] = cc;
            hv[j] = sigf(zo) * tanhf_(cc);
        }
    }
    *(float4*)&hdst[0] = make_float4(hv[0], hv[1], hv[2], hv[3]);
    *(float4*)&hdst[4] = make_float4(hv[4], hv[5], hv[6], hv[7]);
}

__device__ __forceinline__ void load_xtile(const float* __restrict__ x,
                                           int b0, int base, int tid) {
    #pragma unroll
    for (int it = 0; it < 2; ++it) {
        int i = tid + it * NT;
        int row = i >> 4, q = (i & 15) << 2;
        float4 v = *(const float4*)(x + (size_t)(b0 + row) * SEQ + base + q);
        sm[XT_O + (q + 0) * 34 + row] = v.x;
        sm[XT_O + (q + 1) * 34 + row] = v.y;
        sm[XT_O + (q + 2) * 34 + row] = v.z;
        sm[XT_O + (q + 3) * 34 + row] = v.w;
    }
}

// load k-slice (h pairs + gate-packed weights) into register buffer b
#define LOADK(K, b) { \
    int ha = HA_O + ((K) << 5) + (((bg + (K)) & 3) << 3); \
    ulonglong2 q0 = *(const ulonglong2*)&sm[ha]; \
    ulonglong2 q1 = *(const ulonglong2*)&sm[ha + 4]; \
    ulonglong2 q2 = *(const ulonglong2*)&sm[ha + 2048]; \
    ulonglong2 q3 = *(const ulonglong2*)&sm[ha + 2048 + 4]; \
    h1r[b][0] = q0.x; h1r[b][1] = q0.y; h1r[b][2] = q1.x; h1r[b][3] = q1.y; \
    h2r[b][0] = q2.x; h2r[b][1] = q2.y; h2r[b][2] = q3.x; h2r[b][3] = q3.y; \
    w1r[b]  = *(const float4*)&sm[WT1_O + (K) * 256 + hid4]; \
    w2ar[b] = *(const float4*)&sm[WT2_O + (K) * 256 + hid4]; \
    w2br[b] = *(const float4*)&sm[WT2_O + ((K) + 64) * 256 + hid4]; }

#define FMA_G(g, wv, accarr, hparr) { \
    u64 s = splat2(wv); \
    fma2(accarr[g][0], s, hparr[0]); fma2(accarr[g][1], s, hparr[1]); \
    fma2(accarr[g][2], s, hparr[2]); fma2(accarr[g][3], s, hparr[3]); }

#define FMAK(b) { \
    FMA_G(0, w1r[b].x,  acc1, h1r[b]); FMA_G(1, w1r[b].y,  acc1, h1r[b]); \
    FMA_G(2, w1r[b].z,  acc1, h1r[b]); FMA_G(3, w1r[b].w,  acc1, h1r[b]); \
    FMA_G(0, w2ar[b].x, acc2, h1r[b]); FMA_G(1, w2ar[b].y, acc2, h1r[b]); \
    FMA_G(2, w2ar[b].z, acc2, h1r[b]); FMA_G(3, w2ar[b].w, acc2, h1r[b]); \
    FMA_G(0, w2br[b].x, acc2, h2r[b]); FMA_G(1, w2br[b].y, acc2, h2r[b]); \
    FMA_G(2, w2br[b].z, acc2, h2r[b]); FMA_G(3, w2br[b].w, acc2, h2r[b]); }

__global__ void __launch_bounds__(NT, 1)
lstm_fused_kernel(const float* __restrict__ x,
                  const float* __restrict__ W_ih1, const float* __restrict__ W_hh1,
                  const float* __restrict__ b_ih1, const float* __restrict__ b_hh1,
                  const float* __restrict__ W_ih2, const float* __restrict__ W_hh2,
                  const float* __restrict__ b_ih2, const float* __restrict__ b_hh2,
                  const float* __restrict__ W_d1, const float* __restrict__ b_d1,
                  const float* __restrict__ W_d2, const float* __restrict__ b_d2,
                  float* __restrict__ out)
{
    const int tid  = threadIdx.x;
    const int lane = tid & 31;
    const int wrp  = tid >> 5;
    const int hid  = ((wrp & 1) << 5) | lane;   // 0..63
    const int bg   = wrp >> 1;                  // 0..3
    const int b0   = blockIdx.x * TB;
    const int octh = ((bg + hid) & 3) << 3;
    const int hid4 = hid << 2;

    // ---- stage weights: gate-packed k-major [k][hid*4 + gate] ----
    for (int i = tid; i < 64 * 256; i += NT) {
        int k = i >> 8, r = i & 255;
        int g = r >> 6, h = r & 63;
        sm[WT1_O + k * 256 + h * 4 + g] = W_hh1[r * 64 + k];
    }
    for (int i = tid; i < 64 * 256; i += NT) {
        int k = i >> 8, r = i & 255;
        int g = r >> 6, h = r & 63;
        sm[WT2_O + k * 256 + h * 4 + g] = W_ih2[r * 64 + k];
    }
    for (int i = tid; i < 64 * 256; i += NT) {
        int k = i >> 8, r = i & 255;
        int g = r >> 6, h = r & 63;
        sm[WT2_O + (64 + k) * 256 + h * 4 + g] = W_hh2[r * 64 + k];
    }
    for (int i = tid; i < 256; i += NT) {
        sm[B1_O + i]  = b_ih1[i] + b_hh1[i];
        sm[B2_O + i]  = b_ih2[i] + b_hh2[i];
        sm[WI1_O + i] = W_ih1[i];
    }
    for (int i = tid; i < 128 * 32; i += NT) sm[HA_O + i] = 0.f;
    load_xtile(x, b0, 0, tid);
    __syncthreads();

    u64   acc1[4][4], acc2[4][4];
    float c1[8], c2[8];
    #pragma unroll
    for (int j = 0; j < 8; ++j) { c1[j] = 0.f; c2[j] = 0.f; }

    float* h1dst = &sm[HA_O + hid * 32 + octh];
    float* h2dst = &sm[HA_O + (64 + hid) * 32 + octh];

    // ---- prologue: layer1 step 0 (h1=0) ----
    {
        u64 xp[4];
        #pragma unroll
        for (int p = 0; p < 4; ++p)
            xp[p] = *(const u64*)&sm[XT_O + 0 * 34 + bg * 8 + 2 * p];
        #pragma unroll
        for (int g = 0; g < 4; ++g) {
            u64 sb = splat2(sm[B1_O + g * 64 + hid]);
            u64 sw = splat2(sm[WI1_O + g * 64 + hid]);
            #pragma unroll
            for (int p = 0; p < 4; ++p) { acc1[g][p] = sb; fma2(acc1[g][p], sw, xp[p]); }
        }
        pointwise(acc1, c1, h1dst);
    }
    __syncthreads();

    for (int t = 0; t < SEQ; ++t) {
        if (((t + 1) & 63) == 0 && (t + 1) < SEQ) {
            load_xtile(x, b0, t + 1, tid);
            __syncthreads();
        }
        const int tt = ((t + 1) < SEQ ? (t + 1) : t) & 63;

        // acc2 = bias2 ; acc1 = bias1 + x(t+1)*w_ih1
        #pragma unroll
        for (int g = 0; g < 4; ++g) {
            u64 s = splat2(sm[B2_O + g * 64 + hid]);
            #pragma unroll
            for (int p = 0; p < 4; ++p) acc2[g][p] = s;
        }
        {
            u64 xp[4];
            #pragma unroll
            for (int p = 0; p < 4; ++p)
                xp[p] = *(const u64*)&sm[XT_O + tt * 34 + bg * 8 + 2 * p];
            #pragma unroll
            for (int g = 0; g < 4; ++g) {
                u64 sb = splat2(sm[B1_O + g * 64 + hid]);
                u64 sw = splat2(sm[WI1_O + g * 64 + hid]);
                #pragma unroll
                for (int p = 0; p < 4; ++p) { acc1[g][p] = sb; fma2(acc1[g][p], sw, xp[p]); }
            }
        }

        // merged k-loop with register double-buffering
        {
            u64 h1r[2][4], h2r[2][4];
            float4 w1r[2], w2ar[2], w2br[2];
            LOADK(0, 0);
            #pragma unroll 2
            for (int k = 0; k < 64; ++k) {
                const int cur = k & 1;
                if (k < 63) LOADK(k + 1, cur ^ 1);
                FMAK(cur);
            }
        }
        __syncthreads();

        pointwise(acc2, c2, h2dst);                    // h2[t]
        if (t + 1 < SEQ) pointwise(acc1, c1, h1dst);   // h1[t+1]
        __syncthreads();
    }

    // ---- dense head on h2[511] (HA rows 64..127) ----
    for (int i = tid; i < 32 * 64; i += NT) sm[XT_O + i] = W_d1[i];
    for (int i = tid; i < 24 * 32; i += NT) sm[HW_O + i] = W_d2[i];
    if (tid < 32) sm[HW_O + 768 + tid] = b_d1[tid];
    if (tid < 24) sm[HW_O + 800 + tid] = b_d2[tid];
    __syncthreads();

    for (int idx = tid; idx < 32 * 32; idx += NT) {
        int b = idx >> 5, j = idx & 31;
        int ob = b >> 3, bl = b & 7;
        float a = sm[HW_O + 768 + j];
        #pragma unroll 8
        for (int k = 0; k < 64; ++k) {
            float hv = sm[HA_O + (64 + k) * 32 + (((ob + k) & 3) << 3) + bl];
            a += hv * sm[XT_O + j * 64 + k];
        }
        sm[HA_O + b * 32 + j] = fmaxf(a, 0.f);
    }
    __syncthreads();
    for (int idx = tid; idx < 32 * 24; idx += NT) {
        int b = idx / 24, o = idx - b * 24;
        float a = sm[HW_O + 800 + o];
        #pragma unroll 8
        for (int j = 0; j < 32; ++j)
            a += sm[HA_O + b * 32 + j] * sm[HW_O + o * 32 + j];
        out[(size_t)(b0 + b) * 24 + o] = a;
    }
}

extern "C" void kernel_launch(void* const* d_in, const int* in_sizes, int n_in,
                              void* d_out, int out_size)
{
    const float* x     = (const float*)d_in[0];
    const float* W_ih1 = (const float*)d_in[1];
    const float* W_hh1 = (const float*)d_in[2];
    const float* b_ih1 = (const float*)d_in[3];
    const float* b_hh1 = (const float*)d_in[4];
    const float* W_ih2 = (const float*)d_in[5];
    const float* W_hh2 = (const float*)d_in[6];
    const float* b_ih2 = (const float*)d_in[7];
    const float* b_hh2 = (const float*)d_in[8];
    const float* W_d1  = (const float*)d_in[9];
    const float* b_d1  = (const float*)d_in[10];
    const float* W_d2  = (const float*)d_in[11];
    const float* b_d2  = (const float*)d_in[12];
    float* out = (float*)d_out;

    cudaFuncSetAttribute(lstm_fused_kernel,
                         cudaFuncAttributeMaxDynamicSharedMemorySize, SM_BYTES);
    lstm_fused_kernel<<<NBLK, NT, SM_BYTES>>>(
        x, W_ih1, W_hh1, b_ih1, b_hh1, W_ih2, W_hh2, b_ih2, b_hh2,
        W_d1, b_d1, W_d2, b_d2, out);
}